// round 2
// baseline (speedup 1.0000x reference)
#include <cuda_runtime.h>
#include <math.h>

#define BATCH 8
#define CDIM 256
#define HW 4096
#define NGRID 256

// ---------------- scratch (static __device__ arrays; no allocation) ----------
__device__ float g_u   [BATCH*HW*CDIM];
__device__ float g_G   [BATCH*HW*3*CDIM];
__device__ float g_yf  [BATCH*HW*CDIM];
__device__ float g_yb  [BATCH*HW*CDIM];
__device__ float g_y   [BATCH*HW*CDIM];
__device__ float g_ygup[BATCH*HW*CDIM];
__device__ float g_v   [BATCH*HW*CDIM];
__device__ float g_vmap[BATCH*HW*CDIM];
__device__ float g_posf[HW*CDIM];
__device__ float g_posg[NGRID*CDIM];
__device__ float g_xg  [BATCH*CDIM*NGRID];
__device__ float g_ug  [BATCH*NGRID*CDIM];
__device__ float g_Gg  [BATCH*NGRID*3*CDIM];
__device__ float g_yg  [BATCH*NGRID*CDIM];
__device__ float g_pum [BATCH*16*CDIM];
__device__ float g_pumg[BATCH*CDIM];
__device__ float g_cvec[BATCH*CDIM];
__device__ float g_cvecg[BATCH*CDIM];
__device__ float g_cpart[BATCH*3*CDIM];
__device__ float g_cpartg[BATCH*3*CDIM];
__device__ float g_chA [BATCH*16*CDIM];
__device__ float g_chB [BATCH*16*CDIM];
__device__ float g_car [BATCH*16*CDIM];

__device__ __forceinline__ float sigf(float x) {
    return __fdividef(1.f, 1.f + __expf(-x));
}

// ---------------- generic tiled fp32 GEMM, BM=128 BN=64 BK=16, 256 thr -------
// modes: 0=+bias+pos, 1=+cpart(768), 2=rho-combine, 3=lam-combine,
//        4=eta-combine, 5=transpose+residual NCHW, 6=+bias
__global__ __launch_bounds__(256, 2)
void gemm_k(const float* __restrict__ A0, const float* __restrict__ A1, const float* __restrict__ A2,
            const float* __restrict__ B0, const float* __restrict__ B1, const float* __restrict__ B2,
            int Ncols, int nseg, int atrans, int hw,
            int mode, const float* __restrict__ bias,
            const float* __restrict__ e1, const float* __restrict__ e2,
            const float* __restrict__ xres, float* __restrict__ out)
{
    __shared__ float As[16][128];
    __shared__ float Bs[16][64];
    const int m0 = blockIdx.y * 128;
    const int n0 = blockIdx.x * 64;
    const int tid = threadIdx.x;
    const int tx = tid & 15, ty = tid >> 4;
    const float* Bp = (n0 < 256) ? B0 : (n0 < 512 ? B1 : B2);
    const int jb = n0 & 255;

    float acc[8][4];
#pragma unroll
    for (int i = 0; i < 8; i++)
#pragma unroll
        for (int j = 0; j < 4; j++) acc[i][j] = 0.f;

    const int Ktot = nseg << 8;
    for (int kt = 0; kt < Ktot; kt += 16) {
        if (!atrans) {
            const float* Ap = (kt < 256) ? A0 : (kt < 512 ? A1 : A2);
            const int ks = kt & 255;
#pragma unroll
            for (int i = 0; i < 2; i++) {
                int idx = tid + (i << 8);
                int row = idx >> 2;
                int kc  = (idx & 3) << 2;
                float4 vv = *(const float4*)(Ap + (size_t)(m0 + row) * 256 + ks + kc);
                As[kc+0][row] = vv.x; As[kc+1][row] = vv.y;
                As[kc+2][row] = vv.z; As[kc+3][row] = vv.w;
            }
        } else {
            const int bb = m0 / hw;
            const float* Ap = A0 + (size_t)bb * 256 * hw + (m0 % hw);
#pragma unroll
            for (int i = 0; i < 8; i++) {
                int idx = tid + (i << 8);
                int k = idx >> 7, mm = idx & 127;
                As[k][mm] = Ap[(size_t)(kt + k) * hw + mm];
            }
        }
        {
            int k = tid >> 4, nn = (tid & 15) << 2;
            *(float4*)&Bs[k][nn] = *(const float4*)(Bp + (size_t)(kt + k) * 256 + jb + nn);
        }
        __syncthreads();
#pragma unroll
        for (int k = 0; k < 16; k++) {
            float af[8], bf4[4];
            *(float4*)(af)     = *(const float4*)&As[k][ty * 8];
            *(float4*)(af + 4) = *(const float4*)&As[k][ty * 8 + 4];
            *(float4*)(bf4)    = *(const float4*)&Bs[k][tx * 4];
#pragma unroll
            for (int i = 0; i < 8; i++)
#pragma unroll
                for (int j = 0; j < 4; j++)
                    acc[i][j] = fmaf(af[i], bf4[j], acc[i][j]);
        }
        __syncthreads();
    }

#pragma unroll
    for (int i = 0; i < 8; i++) {
        int m = m0 + ty * 8 + i;
#pragma unroll
        for (int j = 0; j < 4; j++) {
            int jc = n0 + tx * 4 + j;
            float a = acc[i][j];
            if (mode == 0) {
                out[(size_t)m * Ncols + jc] = a + bias[jc] + e1[(size_t)(m % hw) * 256 + jc];
            } else if (mode == 1) {
                out[(size_t)m * Ncols + jc] = a + e1[(size_t)(m / hw) * 768 + jc];
            } else if (mode == 2) {
                float r = sigf(a + bias[jc]);
                size_t o = (size_t)m * 256 + jc;
                out[o] = r * e1[o] + (1.f - r) * e2[o];
            } else if (mode == 3) {
                float l = sigf(a + bias[jc]);
                size_t o = (size_t)m * 256 + jc;
                out[o] = e1[o] + l * e2[o];
            } else if (mode == 4) {
                float e = sigf(a + bias[jc]);
                size_t o = (size_t)m * 256 + jc;
                out[o] = e * e1[o] + (1.f - e) * e2[o];
            } else if (mode == 5) {
                int b2 = m / hw, mm = m % hw;
                size_t o = ((size_t)b2 * 256 + jc) * (size_t)hw + mm;
                out[o] = xres[o] + a + bias[jc];
            } else {
                out[(size_t)m * 256 + jc] = a + bias[jc];
            }
        }
    }
}

// ---------------- elementwise / reduction kernels ---------------------------
__global__ void pos_up_k(const float* __restrict__ pos, float* __restrict__ out)
{   // [256,32,32] -> [4096,256], bilinear x2 half-pixel (edge renorm == clamp)
    int t = blockIdx.x * 256 + threadIdx.x;
    int c = t & 255, n = t >> 8;
    int ox = n & 63, oy = n >> 6;
    float sy = (oy + 0.5f) * 0.5f - 0.5f;
    float sx = (ox + 0.5f) * 0.5f - 0.5f;
    int y0 = (int)floorf(sy); float fy = sy - y0;
    int x0 = (int)floorf(sx); float fx = sx - x0;
    int y0c = max(y0, 0), y1c = min(y0 + 1, 31);
    int x0c = max(x0, 0), x1c = min(x0 + 1, 31);
    const float* p = pos + c * 1024;
    out[t] = (1.f - fy) * ((1.f - fx) * p[y0c * 32 + x0c] + fx * p[y0c * 32 + x1c])
           +        fy  * ((1.f - fx) * p[y1c * 32 + x0c] + fx * p[y1c * 32 + x1c]);
}

__global__ void pos_down_k(const float* __restrict__ pos, float* __restrict__ out)
{   // [256,32,32] -> [256(tokens),256(ch)], antialiased linear downsample x2
    int t = blockIdx.x * 256 + threadIdx.x;
    int c = t & 255, ng = t >> 8;
    int gx = ng & 15, gy = ng >> 4;
    const float bw4[4] = {0.125f, 0.375f, 0.375f, 0.125f};
    float wy[4], wx[4]; int iy[4], ix[4];
    float sy = 0.f, sx = 0.f;
#pragma unroll
    for (int k = 0; k < 4; k++) {
        int yv = 2 * gy - 1 + k;
        if (yv >= 0 && yv < 32) { iy[k] = yv; wy[k] = bw4[k]; sy += bw4[k]; }
        else { iy[k] = 0; wy[k] = 0.f; }
        int xv = 2 * gx - 1 + k;
        if (xv >= 0 && xv < 32) { ix[k] = xv; wx[k] = bw4[k]; sx += bw4[k]; }
        else { ix[k] = 0; wx[k] = 0.f; }
    }
    const float* p = pos + c * 1024;
    float acc = 0.f;
#pragma unroll
    for (int a = 0; a < 4; a++)
#pragma unroll
        for (int b2 = 0; b2 < 4; b2++)
            acc += wy[a] * wx[b2] * p[iy[a] * 32 + ix[b2]];
    out[t] = acc * __fdividef(1.f, sy * sx);
}

__global__ void pool_k(const float* __restrict__ x, float* __restrict__ xg)
{   // 4x4 exact avg pool, out [B,C,256] NCHW-like
    int t = blockIdx.x * 256 + threadIdx.x;
    int gx = t & 15, gy = (t >> 4) & 15;
    int c = (t >> 8) & 255, b = t >> 16;
    const float* p = x + ((size_t)b * 256 + c) * 4096 + gy * 256 + gx * 4;
    float s = 0.f;
#pragma unroll
    for (int i = 0; i < 4; i++)
#pragma unroll
        for (int j = 0; j < 4; j++) s += p[i * 64 + j];
    xg[t] = s * 0.0625f;
}

__global__ void dwconv_k(const float* __restrict__ x, const float* __restrict__ w,
                         const float* __restrict__ bwt, float* __restrict__ vmap)
{
    int t = blockIdx.x * 256 + threadIdx.x;
    int xx = t & 63, yy = (t >> 6) & 63, c = (t >> 12) & 255, b = t >> 20;
    const float* xp = x + ((size_t)b * 256 + c) * 4096;
    const float* wp = w + c * 9;
    float acc = bwt[c];
#pragma unroll
    for (int ky = 0; ky < 3; ky++) {
        int y2 = yy + ky - 1;
        if ((unsigned)y2 < 64u) {
#pragma unroll
            for (int kx = 0; kx < 3; kx++) {
                int x2 = xx + kx - 1;
                if ((unsigned)x2 < 64u) acc = fmaf(xp[y2 * 64 + x2], wp[ky * 3 + kx], acc);
            }
        }
    }
    vmap[t] = acc;
}

__global__ void yg_up_k(const float* __restrict__ yg, float* __restrict__ out)
{   // [B,256(16x16),C] -> [B,4096,C], bilinear x4 half-pixel (clamp)
    int t = blockIdx.x * 256 + threadIdx.x;
    int c = t & 255, n = (t >> 8) & 4095, b = t >> 20;
    int ox = n & 63, oy = n >> 6;
    float sy = (oy + 0.5f) * 0.25f - 0.5f;
    float sx = (ox + 0.5f) * 0.25f - 0.5f;
    int y0 = (int)floorf(sy); float fy = sy - y0;
    int x0 = (int)floorf(sx); float fx = sx - x0;
    int y0c = max(y0, 0), y1c = min(y0 + 1, 15);
    int x0c = max(x0, 0), x1c = min(x0 + 1, 15);
    const float* p = yg + (size_t)b * 65536;
    float v00 = p[(y0c * 16 + x0c) * 256 + c], v01 = p[(y0c * 16 + x1c) * 256 + c];
    float v10 = p[(y1c * 16 + x0c) * 256 + c], v11 = p[(y1c * 16 + x1c) * 256 + c];
    out[t] = (1.f - fy) * ((1.f - fx) * v00 + fx * v01) + fy * ((1.f - fx) * v10 + fx * v11);
}

__global__ void colsum_k(const float* __restrict__ src, float* __restrict__ dst, int rows)
{
    int c = threadIdx.x;
    size_t r0 = (size_t)blockIdx.x * rows;
    float s = 0.f;
    for (int r = 0; r < rows; r++) s += src[(r0 + r) * 256 + c];
    dst[blockIdx.x * 256 + c] = s;
}

__global__ void ln_k(const float* __restrict__ part, int nch, float invRows,
                     const float* __restrict__ lng, const float* __restrict__ lnb,
                     float* __restrict__ cvec)
{
    __shared__ float red[256];
    int b = blockIdx.x, c = threadIdx.x;
    float um = 0.f;
    for (int i = 0; i < nch; i++) um += part[(b * nch + i) * 256 + c];
    um *= invRows;
    red[c] = um; __syncthreads();
    for (int st = 128; st; st >>= 1) { if (c < st) red[c] += red[c + st]; __syncthreads(); }
    float mean = red[0] * (1.f / 256.f);
    __syncthreads();
    float dv = um - mean;
    red[c] = dv * dv; __syncthreads();
    for (int st = 128; st; st >>= 1) { if (c < st) red[c] += red[c + st]; __syncthreads(); }
    float var = red[0] * (1.f / 256.f);
    cvec[b * 256 + c] = dv * rsqrtf(var + 1e-5f) * lng[c] + lnb[c];
}

__global__ void cpart_k(const float* __restrict__ cvec,
                        const float* __restrict__ Wf, const float* __restrict__ Ww,
                        const float* __restrict__ Wo,
                        const float* __restrict__ bf, const float* __restrict__ bw,
                        const float* __restrict__ bo, float* __restrict__ cp)
{
    int b = blockIdx.x / 3, seg = blockIdx.x % 3;
    int jj = threadIdx.x;
    const float* W  = seg == 0 ? Wf : (seg == 1 ? Ww : Wo);
    const float* bi = seg == 0 ? bf : (seg == 1 ? bw : bo);
    float acc = bi[jj];
    const float* cv = cvec + b * 256;
    for (int cc = 0; cc < 256; cc++) acc = fmaf(cv[cc], W[(256 + cc) * 256 + jj], acc);
    cp[b * 768 + seg * 256 + jj] = acc;
}

// ---------------- chunked linear-recurrence scans (fine branch, N=4096) ------
// a = sigmoid(-d), 1-a = sigmoid(d), b = (1-a)*sigmoid(w)*u
__global__ void scan_aggr_k(const float* __restrict__ G, const float* __restrict__ U,
                            float* __restrict__ chA, float* __restrict__ chB, int backward)
{
    int w = blockIdx.x * 8 + (threadIdx.x >> 5);
    int lane = threadIdx.x & 31;
    int c  = ((w & 7) << 5) + lane;
    int ch = (w >> 3) & 15;
    int b  = w >> 7;
    float s = 0.f, Ap = 1.f;
    int n0 = ch << 8;
#pragma unroll 4
    for (int r = 0; r < 256; r++) {
        int n = backward ? (n0 + 255 - r) : (n0 + r);
        size_t row = (size_t)(b * 4096 + n);
        float d  = fminf(G[row * 768 + c], 80.f);
        float wl = G[row * 768 + 256 + c];
        float uu = U[row * 256 + c];
        float e = __expf(d);
        float inv = __fdividef(1.f, 1.f + e);
        float bb = (e * inv) * sigf(wl) * uu;
        s = fmaf(inv, s, bb);
        Ap *= inv;
    }
    int o = (b * 16 + ch) * 256 + c;
    chA[o] = Ap; chB[o] = s;
}

__global__ void scan_comb_k(const float* __restrict__ chA, const float* __restrict__ chB,
                            float* __restrict__ carry, int backward)
{
    int b = blockIdx.x, c = threadIdx.x;
    float s = 0.f;
    for (int i = 0; i < 16; i++) {
        int ch = backward ? 15 - i : i;
        int o = (b * 16 + ch) * 256 + c;
        carry[o] = s;
        s = fmaf(chA[o], s, chB[o]);
    }
}

__global__ void scan_fin_k(const float* __restrict__ G, const float* __restrict__ U,
                           const float* __restrict__ carry, float* __restrict__ Y, int backward)
{
    int w = blockIdx.x * 8 + (threadIdx.x >> 5);
    int lane = threadIdx.x & 31;
    int c  = ((w & 7) << 5) + lane;
    int ch = (w >> 3) & 15;
    int b  = w >> 7;
    float s = carry[(b * 16 + ch) * 256 + c];
    int n0 = ch << 8;
#pragma unroll 4
    for (int r = 0; r < 256; r++) {
        int n = backward ? (n0 + 255 - r) : (n0 + r);
        size_t row = (size_t)(b * 4096 + n);
        float d  = fminf(G[row * 768 + c], 80.f);
        float wl = G[row * 768 + 256 + c];
        float ol = G[row * 768 + 512 + c];
        float uu = U[row * 256 + c];
        float e = __expf(d);
        float inv = __fdividef(1.f, 1.f + e);
        float bb = (e * inv) * sigf(wl) * uu;
        s = fmaf(inv, s, bb);
        float o = sigf(ol);
        Y[row * 256 + c] = o * s + (1.f - o) * uu;
    }
}

__global__ void scan_global_k(const float* __restrict__ G, const float* __restrict__ U,
                              float* __restrict__ Y)
{   // forward scan, N=256, one block per batch, thread=channel
    int b = blockIdx.x, c = threadIdx.x;
    float s = 0.f;
    for (int n = 0; n < 256; n++) {
        size_t row = (size_t)(b * 256 + n);
        float d  = fminf(G[row * 768 + c], 80.f);
        float wl = G[row * 768 + 256 + c];
        float ol = G[row * 768 + 512 + c];
        float uu = U[row * 256 + c];
        float e = __expf(d);
        float inv = __fdividef(1.f, 1.f + e);
        float bb = (e * inv) * sigf(wl) * uu;
        s = fmaf(inv, s, bb);
        float o = sigf(ol);
        Y[row * 256 + c] = o * s + (1.f - o) * uu;
    }
}

// ---------------------------------------------------------------------------
extern "C" void kernel_launch(void* const* d_in, const int* in_sizes, int n_in,
                              void* d_out, int out_size)
{
    const float* x    = (const float*)d_in[0];
    const float* Wt   = (const float*)d_in[1];
    const float* bt   = (const float*)d_in[2];
    const float* posf = (const float*)d_in[3];
    const float* posg = (const float*)d_in[4];
    const float* lng  = (const float*)d_in[5];
    const float* lnb  = (const float*)d_in[6];
    const float* Wf   = (const float*)d_in[7];
    const float* bf   = (const float*)d_in[8];
    const float* Ww   = (const float*)d_in[9];
    const float* bw   = (const float*)d_in[10];
    const float* Wo   = (const float*)d_in[11];
    const float* bo   = (const float*)d_in[12];
    const float* Wr   = (const float*)d_in[13];
    const float* br   = (const float*)d_in[14];
    const float* Wgi  = (const float*)d_in[15];
    const float* bgi  = (const float*)d_in[16];
    const float* dww  = (const float*)d_in[17];
    const float* dwb  = (const float*)d_in[18];
    const float* Wl   = (const float*)d_in[19];
    const float* bl   = (const float*)d_in[20];
    const float* Wlf  = (const float*)d_in[21];
    const float* blf  = (const float*)d_in[22];
    const float* Wout = (const float*)d_in[23];
    const float* bout = (const float*)d_in[24];
    float* out = (float*)d_out;

    float *pu, *pG, *pyf, *pyb, *py, *pyg_up, *pv, *pvmap, *pposf, *pposg,
          *pxg, *pug, *pGg, *pyg, *ppum, *ppumg, *pcvec, *pcvecg, *pcpart,
          *pcpartg, *pchA, *pchB, *pcar;
    cudaGetSymbolAddress((void**)&pu, g_u);
    cudaGetSymbolAddress((void**)&pG, g_G);
    cudaGetSymbolAddress((void**)&pyf, g_yf);
    cudaGetSymbolAddress((void**)&pyb, g_yb);
    cudaGetSymbolAddress((void**)&py, g_y);
    cudaGetSymbolAddress((void**)&pyg_up, g_ygup);
    cudaGetSymbolAddress((void**)&pv, g_v);
    cudaGetSymbolAddress((void**)&pvmap, g_vmap);
    cudaGetSymbolAddress((void**)&pposf, g_posf);
    cudaGetSymbolAddress((void**)&pposg, g_posg);
    cudaGetSymbolAddress((void**)&pxg, g_xg);
    cudaGetSymbolAddress((void**)&pug, g_ug);
    cudaGetSymbolAddress((void**)&pGg, g_Gg);
    cudaGetSymbolAddress((void**)&pyg, g_yg);
    cudaGetSymbolAddress((void**)&ppum, g_pum);
    cudaGetSymbolAddress((void**)&ppumg, g_pumg);
    cudaGetSymbolAddress((void**)&pcvec, g_cvec);
    cudaGetSymbolAddress((void**)&pcvecg, g_cvecg);
    cudaGetSymbolAddress((void**)&pcpart, g_cpart);
    cudaGetSymbolAddress((void**)&pcpartg, g_cpartg);
    cudaGetSymbolAddress((void**)&pchA, g_chA);
    cudaGetSymbolAddress((void**)&pchB, g_chB);
    cudaGetSymbolAddress((void**)&pcar, g_car);

    // pos embeds
    pos_up_k<<<4096, 256>>>(posf, pposf);
    pos_down_k<<<256, 256>>>(posg, pposg);

    // u = seq@Wt + bt + posf   (A transposed-read from NCHW x)
    gemm_k<<<dim3(4, 256), 256>>>(x, x, x, Wt, Wt, Wt, 256, 1, 1, 4096,
                                  0, bt, pposf, pposf, x, pu);
    // global: pool, u_g
    pool_k<<<2048, 256>>>(x, pxg);
    gemm_k<<<dim3(4, 16), 256>>>(pxg, pxg, pxg, Wt, Wt, Wt, 256, 1, 1, 256,
                                 0, bt, pposg, pposg, x, pug);

    // LN context + cpart (fine + global)
    colsum_k<<<128, 256>>>(pu, ppum, 256);
    ln_k<<<8, 256>>>(ppum, 16, 1.f / 4096.f, lng, lnb, pcvec);
    cpart_k<<<24, 256>>>(pcvec, Wf, Ww, Wo, bf, bw, bo, pcpart);
    colsum_k<<<8, 256>>>(pug, ppumg, 256);
    ln_k<<<8, 256>>>(ppumg, 1, 1.f / 256.f, lng, lnb, pcvecg);
    cpart_k<<<24, 256>>>(pcvecg, Wf, Ww, Wo, bf, bw, bo, pcpartg);

    // gate pre-activations (shared by fwd+bwd): G = u@Wtop + cpart
    gemm_k<<<dim3(12, 256), 256>>>(pu, pu, pu, Wf, Ww, Wo, 768, 1, 0, 4096,
                                   1, bf, pcpart, pcpart, x, pG);
    gemm_k<<<dim3(12, 16), 256>>>(pug, pug, pug, Wf, Ww, Wo, 768, 1, 0, 256,
                                  1, bf, pcpartg, pcpartg, x, pGg);

    // scans
    scan_aggr_k<<<128, 256>>>(pG, pu, pchA, pchB, 0);
    scan_comb_k<<<8, 256>>>(pchA, pchB, pcar, 0);
    scan_fin_k<<<128, 256>>>(pG, pu, pcar, pyf, 0);
    scan_aggr_k<<<128, 256>>>(pG, pu, pchA, pchB, 1);
    scan_comb_k<<<8, 256>>>(pchA, pchB, pcar, 1);
    scan_fin_k<<<128, 256>>>(pG, pu, pcar, pyb, 1);
    scan_global_k<<<8, 256>>>(pGg, pug, pyg);

    // rho combine: y = rho*yf + (1-rho)*yb
    gemm_k<<<dim3(4, 256), 256>>>(pu, pyf, pyb, Wr, Wr, Wr, 256, 3, 0, 4096,
                                  2, br, pyf, pyb, x, py);

    // global upsample
    yg_up_k<<<32768, 256>>>(pyg, pyg_up);

    // lam combine: z = y + lam*ygup   (write into g_yb, now free)
    gemm_k<<<dim3(4, 256), 256>>>(py, pyg_up, pu, Wgi, Wgi, Wgi, 256, 3, 0, 4096,
                                  3, bgi, py, pyg_up, x, pyb);

    // local branch
    dwconv_k<<<32768, 256>>>(x, dww, dwb, pvmap);
    gemm_k<<<dim3(4, 256), 256>>>(pvmap, pvmap, pvmap, Wl, Wl, Wl, 256, 1, 1, 4096,
                                  6, bl, py, py, x, pv);

    // eta combine: u_out = eta*v + (1-eta)*z  (write into g_yf, now free)
    gemm_k<<<dim3(4, 256), 256>>>(pv, pyb, pyb, Wlf, Wlf, Wlf, 256, 2, 0, 4096,
                                  4, blf, pv, pyb, x, pyf);

    // out-proj + residual, transposed write to NCHW
    gemm_k<<<dim3(4, 256), 256>>>(pyf, pyf, pyf, Wout, Wout, Wout, 256, 1, 0, 4096,
                                  5, bout, py, py, x, out);
}

// round 5
// speedup vs baseline: 2.5114x; 2.5114x over previous
#include <cuda_runtime.h>
#include <cuda_bf16.h>
#include <math.h>
#include <stdint.h>

#define BATCH 8
#define CDIM 256
#define HW 4096
#define NGRID 256

// ---------------- scratch (static __device__ arrays; no allocation) ----------
__device__ float g_u   [BATCH*HW*CDIM];
__device__ float g_G   [BATCH*HW*3*CDIM];
__device__ float g_yf  [BATCH*HW*CDIM];
__device__ float g_yb  [BATCH*HW*CDIM];
__device__ float g_y   [BATCH*HW*CDIM];
__device__ float g_ygup[BATCH*HW*CDIM];
__device__ float g_v   [BATCH*HW*CDIM];
__device__ float g_vmap[BATCH*HW*CDIM];
__device__ float g_xseq[BATCH*HW*CDIM];
__device__ float g_vmseq[BATCH*HW*CDIM];
__device__ float g_posf[HW*CDIM];
__device__ float g_posg[NGRID*CDIM];
__device__ float g_xg  [BATCH*CDIM*NGRID];
__device__ float g_xgseq[BATCH*NGRID*CDIM];
__device__ float g_ug  [BATCH*NGRID*CDIM];
__device__ float g_Gg  [BATCH*NGRID*3*CDIM];
__device__ float g_yg  [BATCH*NGRID*CDIM];
__device__ float g_pum [BATCH*16*CDIM];
__device__ float g_pumg[BATCH*CDIM];
__device__ float g_cvec[BATCH*CDIM];
__device__ float g_cvecg[BATCH*CDIM];
__device__ float g_cpart[BATCH*3*CDIM];
__device__ float g_cpartg[BATCH*3*CDIM];
__device__ float g_chA [BATCH*16*CDIM];
__device__ float g_chB [BATCH*16*CDIM];
__device__ float g_car [BATCH*16*CDIM];
__device__ __nv_bfloat16 g_BT[917504];   // transposed bf16 weights

// BT offsets (elements)
#define BT_T   0
#define BT_F   65536
#define BT_W2  131072
#define BT_O   196608
#define BT_R   262144
#define BT_GI  458752
#define BT_L   655360
#define BT_LF  720896
#define BT_OUT 851968

__device__ __forceinline__ float sigf(float x) {
    return __fdividef(1.f, 1.f + __expf(-x));
}

__device__ __forceinline__ void mma16816(float* c, const uint32_t* a, const uint32_t* b) {
    asm volatile(
        "mma.sync.aligned.m16n8k16.row.col.f32.bf16.bf16.f32 "
        "{%0,%1,%2,%3}, {%4,%5,%6,%7}, {%8,%9}, {%0,%1,%2,%3};"
        : "+f"(c[0]), "+f"(c[1]), "+f"(c[2]), "+f"(c[3])
        : "r"(a[0]), "r"(a[1]), "r"(a[2]), "r"(a[3]), "r"(b[0]), "r"(b[1]));
}

// ======================= tensor-core GEMM (HMMA mma.sync) ====================
// out tile = sum_k A[M,K] @ B^T  with B^T given as [N,K] bf16 rows.
// A supplied in up-to-3 fp32 chunks of K=256 each (concat along K).
// modes: 0=+bias+pos, 1=+cpart, 2=rho, 3=lam, 4=eta, 5=NCHW residual, 6=+bias
#define SPAD 40
__global__ __launch_bounds__(256)
void tgemm_k(const float* __restrict__ A0, const float* __restrict__ A1,
             const float* __restrict__ A2,
             const __nv_bfloat16* __restrict__ B0, const __nv_bfloat16* __restrict__ B1,
             const __nv_bfloat16* __restrict__ B2,
             int Kw, int Ktot, int mode, int hw, int ostr,
             const float* __restrict__ bias, const float* __restrict__ e1,
             const float* __restrict__ e2, const float* __restrict__ xres,
             float* __restrict__ out)
{
    __shared__ __align__(16) __nv_bfloat16 sA[2][128][SPAD];
    __shared__ __align__(16) __nv_bfloat16 sB[2][128][SPAD];

    const int tid = threadIdx.x;
    const int lane = tid & 31, wid = tid >> 5;
    const int wm = wid & 3, wn = wid >> 2;
    const int m0 = blockIdx.y * 128;
    const int n0g = blockIdx.x * 128;
    const int seg = n0g >> 8;
    const __nv_bfloat16* Bp = seg == 0 ? B0 : (seg == 1 ? B1 : B2);
    const int jb = n0g & 255;

    // per-thread load coords
    const int arow = tid >> 3, akc = (tid & 7) << 2;      // A: 4 float4 slots, +32 rows each
    const int brow = tid >> 2, bkc = (tid & 3) << 3;      // B: 2 uint4 slots, +64 rows each

    float acc[2][8][4];
#pragma unroll
    for (int i = 0; i < 2; i++)
#pragma unroll
        for (int j = 0; j < 8; j++)
#pragma unroll
            for (int l = 0; l < 4; l++) acc[i][j][l] = 0.f;

    float4 pa[4];
    uint4  pb[2];

    // ---- prologue fetch kt=0 ----
    {
        const float* Ap = A0;
#pragma unroll
        for (int i = 0; i < 4; i++)
            pa[i] = *(const float4*)(Ap + (size_t)(m0 + arow + i * 32) * 256 + akc);
#pragma unroll
        for (int i = 0; i < 2; i++)
            pb[i] = *(const uint4*)(Bp + (size_t)(jb + brow + i * 64) * Kw + bkc);
    }
#pragma unroll
    for (int i = 0; i < 4; i++) {
        __nv_bfloat162 h0 = __floats2bfloat162_rn(pa[i].x, pa[i].y);
        __nv_bfloat162 h1 = __floats2bfloat162_rn(pa[i].z, pa[i].w);
        *(__nv_bfloat162*)&sA[0][arow + i * 32][akc]     = h0;
        *(__nv_bfloat162*)&sA[0][arow + i * 32][akc + 2] = h1;
    }
#pragma unroll
    for (int i = 0; i < 2; i++) {
        *(uint2*)&sB[0][brow + i * 64][bkc]     = make_uint2(pb[i].x, pb[i].y);
        *(uint2*)&sB[0][brow + i * 64][bkc + 4] = make_uint2(pb[i].z, pb[i].w);
    }
    __syncthreads();

    int buf = 0;
    for (int kt = 0; kt < Ktot; kt += 32) {
        const bool more = (kt + 32) < Ktot;
        if (more) {
            int kn = kt + 32;
            const float* Ap = (kn < 256) ? A0 : (kn < 512 ? A1 : A2);
            int ks2 = kn & 255;
#pragma unroll
            for (int i = 0; i < 4; i++)
                pa[i] = *(const float4*)(Ap + (size_t)(m0 + arow + i * 32) * 256 + ks2 + akc);
#pragma unroll
            for (int i = 0; i < 2; i++)
                pb[i] = *(const uint4*)(Bp + (size_t)(jb + brow + i * 64) * Kw + kn + bkc);
        }
        // ---- compute on buf ----
        const uint32_t* pA = (const uint32_t*)&sA[buf][0][0];
        const uint32_t* pB = (const uint32_t*)&sB[buf][0][0];
#pragma unroll
        for (int ks = 0; ks < 32; ks += 16) {
            const int kb = (ks + ((lane & 3) << 1)) >> 1;   // uint32 index
            uint32_t aF[2][4];
#pragma unroll
            for (int ma = 0; ma < 2; ma++) {
                int r = wm * 32 + ma * 16 + (lane >> 2);
                aF[ma][0] = pA[r * (SPAD/2) + kb];
                aF[ma][1] = pA[(r + 8) * (SPAD/2) + kb];
                aF[ma][2] = pA[r * (SPAD/2) + kb + 4];
                aF[ma][3] = pA[(r + 8) * (SPAD/2) + kb + 4];
            }
            uint32_t bF[8][2];
#pragma unroll
            for (int na = 0; na < 8; na++) {
                int n = wn * 64 + na * 8 + (lane >> 2);
                bF[na][0] = pB[n * (SPAD/2) + kb];
                bF[na][1] = pB[n * (SPAD/2) + kb + 4];
            }
#pragma unroll
            for (int ma = 0; ma < 2; ma++)
#pragma unroll
                for (int na = 0; na < 8; na++)
                    mma16816(acc[ma][na], aF[ma], bF[na]);
        }
        if (more) {
            int nb = buf ^ 1;
#pragma unroll
            for (int i = 0; i < 4; i++) {
                __nv_bfloat162 h0 = __floats2bfloat162_rn(pa[i].x, pa[i].y);
                __nv_bfloat162 h1 = __floats2bfloat162_rn(pa[i].z, pa[i].w);
                *(__nv_bfloat162*)&sA[nb][arow + i * 32][akc]     = h0;
                *(__nv_bfloat162*)&sA[nb][arow + i * 32][akc + 2] = h1;
            }
#pragma unroll
            for (int i = 0; i < 2; i++) {
                *(uint2*)&sB[nb][brow + i * 64][bkc]     = make_uint2(pb[i].x, pb[i].y);
                *(uint2*)&sB[nb][brow + i * 64][bkc + 4] = make_uint2(pb[i].z, pb[i].w);
            }
        }
        __syncthreads();
        buf ^= 1;
    }

    // ---- epilogue straight from accumulators ----
#pragma unroll
    for (int ma = 0; ma < 2; ma++) {
#pragma unroll
        for (int na = 0; na < 8; na++) {
            int mb = m0 + wm * 32 + ma * 16 + (lane >> 2);
            int jc0 = n0g + wn * 64 + na * 8 + ((lane & 3) << 1);
#pragma unroll
            for (int h = 0; h < 2; h++) {       // row +0 / +8
                int m = mb + h * 8;
#pragma unroll
                for (int q = 0; q < 2; q++) {   // col pair
                    int jc = jc0 + q;
                    float a = acc[ma][na][h * 2 + q];
                    if (mode == 0) {
                        out[(size_t)m * ostr + jc] = a + bias[jc] + e1[(size_t)(m % hw) * 256 + jc];
                    } else if (mode == 1) {
                        out[(size_t)m * ostr + jc] = a + e1[(size_t)(m / hw) * 768 + jc];
                    } else if (mode == 6) {
                        out[(size_t)m * ostr + jc] = a + bias[jc];
                    } else if (mode == 5) {
                        int b2 = m >> 12, mm = m & 4095;
                        size_t o = (((size_t)(b2 * 256 + jc)) << 12) + mm;
                        out[o] = xres[o] + a + bias[jc];
                    } else {
                        size_t o = (size_t)m * 256 + jc;
                        float s = sigf(a + bias[jc]);
                        if (mode == 3) out[o] = e1[o] + s * e2[o];
                        else           out[o] = s * e1[o] + (1.f - s) * e2[o];
                    }
                }
            }
        }
    }
}

// ======================= weight prep: W[K,256] -> BT[256,K] bf16 =============
__global__ void wprep_k(const float* __restrict__ Wt, const float* __restrict__ Wf,
                        const float* __restrict__ Ww, const float* __restrict__ Wo,
                        const float* __restrict__ Wr, const float* __restrict__ Wgi,
                        const float* __restrict__ Wl, const float* __restrict__ Wlf,
                        const float* __restrict__ Wout, __nv_bfloat16* __restrict__ BT)
{
    int id = blockIdx.x;
    const float* src; int Kt; size_t boff;
    if (id < 64)       { src = Wt;   Kt = 256; boff = BT_T; }
    else if (id < 128) { src = Wf;   Kt = 256; boff = BT_F;   id -= 64; }
    else if (id < 192) { src = Ww;   Kt = 256; boff = BT_W2;  id -= 128; }
    else if (id < 256) { src = Wo;   Kt = 256; boff = BT_O;   id -= 192; }
    else if (id < 448) { src = Wr;   Kt = 768; boff = BT_R;   id -= 256; }
    else if (id < 640) { src = Wgi;  Kt = 768; boff = BT_GI;  id -= 448; }
    else if (id < 704) { src = Wl;   Kt = 256; boff = BT_L;   id -= 640; }
    else if (id < 832) { src = Wlf;  Kt = 512; boff = BT_LF;  id -= 704; }
    else               { src = Wout; Kt = 256; boff = BT_OUT; id -= 832; }
    int ktiles = Kt / 32;
    int k0 = (id % ktiles) * 32, n0 = (id / ktiles) * 32;
    __shared__ float t[32][33];
    int tx = threadIdx.x & 31, ty = threadIdx.x >> 5;
#pragma unroll
    for (int i = 0; i < 4; i++)
        t[ty + i * 8][tx] = src[(size_t)(k0 + ty + i * 8) * 256 + n0 + tx];
    __syncthreads();
    __nv_bfloat16* bp = BT + boff;
#pragma unroll
    for (int i = 0; i < 4; i++) {
        int n = n0 + ty + i * 8;
        bp[(size_t)n * Kt + k0 + tx] = __float2bfloat16(t[tx][ty + i * 8]);
    }
}

// ======================= NCHW [B,256,hw] -> seq [B*hw,256] fp32 ==============
__global__ void nchw2seq_k(const float* __restrict__ in, float* __restrict__ outp, int hw)
{
    __shared__ float t[32][33];
    int m0 = blockIdx.x * 32, c0 = blockIdx.y * 32, b = blockIdx.z;
    int tx = threadIdx.x & 31, ty = threadIdx.x >> 5;
    const float* ip = in + (size_t)b * 256 * hw;
#pragma unroll
    for (int i = 0; i < 4; i++)
        t[ty + i * 8][tx] = ip[(size_t)(c0 + ty + i * 8) * hw + m0 + tx];
    __syncthreads();
    float* op = outp + (size_t)b * hw * 256;
#pragma unroll
    for (int i = 0; i < 4; i++) {
        int m = m0 + ty + i * 8;
        op[(size_t)m * 256 + c0 + tx] = t[tx][ty + i * 8];
    }
}

// ======================= elementwise / small kernels =========================
__global__ void pos_up_k(const float* __restrict__ pos, float* __restrict__ out)
{
    int t = blockIdx.x * 256 + threadIdx.x;
    int c = t & 255, n = t >> 8;
    int ox = n & 63, oy = n >> 6;
    float sy = (oy + 0.5f) * 0.5f - 0.5f;
    float sx = (ox + 0.5f) * 0.5f - 0.5f;
    int y0 = (int)floorf(sy); float fy = sy - y0;
    int x0 = (int)floorf(sx); float fx = sx - x0;
    int y0c = max(y0, 0), y1c = min(y0 + 1, 31);
    int x0c = max(x0, 0), x1c = min(x0 + 1, 31);
    const float* p = pos + c * 1024;
    out[t] = (1.f - fy) * ((1.f - fx) * p[y0c * 32 + x0c] + fx * p[y0c * 32 + x1c])
           +        fy  * ((1.f - fx) * p[y1c * 32 + x0c] + fx * p[y1c * 32 + x1c]);
}

__global__ void pos_down_k(const float* __restrict__ pos, float* __restrict__ out)
{
    int t = blockIdx.x * 256 + threadIdx.x;
    int c = t & 255, ng = t >> 8;
    int gx = ng & 15, gy = ng >> 4;
    const float bw4[4] = {0.125f, 0.375f, 0.375f, 0.125f};
    float wy[4], wx[4]; int iy[4], ix[4];
    float sy = 0.f, sx = 0.f;
#pragma unroll
    for (int k = 0; k < 4; k++) {
        int yv = 2 * gy - 1 + k;
        if (yv >= 0 && yv < 32) { iy[k] = yv; wy[k] = bw4[k]; sy += bw4[k]; }
        else { iy[k] = 0; wy[k] = 0.f; }
        int xv = 2 * gx - 1 + k;
        if (xv >= 0 && xv < 32) { ix[k] = xv; wx[k] = bw4[k]; sx += bw4[k]; }
        else { ix[k] = 0; wx[k] = 0.f; }
    }
    const float* p = pos + c * 1024;
    float acc = 0.f;
#pragma unroll
    for (int a = 0; a < 4; a++)
#pragma unroll
        for (int b2 = 0; b2 < 4; b2++)
            acc += wy[a] * wx[b2] * p[iy[a] * 32 + ix[b2]];
    out[t] = acc * __fdividef(1.f, sy * sx);
}

__global__ void pool_k(const float* __restrict__ x, float* __restrict__ xg)
{
    int t = blockIdx.x * 256 + threadIdx.x;
    int gx = t & 15, gy = (t >> 4) & 15;
    int c = (t >> 8) & 255, b = t >> 16;
    const float* p = x + ((size_t)b * 256 + c) * 4096 + gy * 256 + gx * 4;
    float s = 0.f;
#pragma unroll
    for (int i = 0; i < 4; i++)
#pragma unroll
        for (int j = 0; j < 4; j++) s += p[i * 64 + j];
    xg[t] = s * 0.0625f;
}

__global__ void dwconv_k(const float* __restrict__ x, const float* __restrict__ w,
                         const float* __restrict__ bwt, float* __restrict__ vmap)
{
    int t = blockIdx.x * 256 + threadIdx.x;
    int xx = t & 63, yy = (t >> 6) & 63, c = (t >> 12) & 255, b = t >> 20;
    const float* xp = x + ((size_t)b * 256 + c) * 4096;
    const float* wp = w + c * 9;
    float acc = bwt[c];
#pragma unroll
    for (int ky = 0; ky < 3; ky++) {
        int y2 = yy + ky - 1;
        if ((unsigned)y2 < 64u) {
#pragma unroll
            for (int kx = 0; kx < 3; kx++) {
                int x2 = xx + kx - 1;
                if ((unsigned)x2 < 64u) acc = fmaf(xp[y2 * 64 + x2], wp[ky * 3 + kx], acc);
            }
        }
    }
    vmap[t] = acc;
}

__global__ void yg_up_k(const float* __restrict__ yg, float* __restrict__ out)
{
    int t = blockIdx.x * 256 + threadIdx.x;
    int c = t & 255, n = (t >> 8) & 4095, b = t >> 20;
    int ox = n & 63, oy = n >> 6;
    float sy = (oy + 0.5f) * 0.25f - 0.5f;
    float sx = (ox + 0.5f) * 0.25f - 0.5f;
    int y0 = (int)floorf(sy); float fy = sy - y0;
    int x0 = (int)floorf(sx); float fx = sx - x0;
    int y0c = max(y0, 0), y1c = min(y0 + 1, 15);
    int x0c = max(x0, 0), x1c = min(x0 + 1, 15);
    const float* p = yg + (size_t)b * 65536;
    float v00 = p[(y0c * 16 + x0c) * 256 + c], v01 = p[(y0c * 16 + x1c) * 256 + c];
    float v10 = p[(y1c * 16 + x0c) * 256 + c], v11 = p[(y1c * 16 + x1c) * 256 + c];
    out[t] = (1.f - fy) * ((1.f - fx) * v00 + fx * v01) + fy * ((1.f - fx) * v10 + fx * v11);
}

__global__ void colsum_k(const float* __restrict__ src, float* __restrict__ dst, int rows)
{
    int c = threadIdx.x;
    size_t r0 = (size_t)blockIdx.x * rows;
    float s = 0.f;
    for (int r = 0; r < rows; r++) s += src[(r0 + r) * 256 + c];
    dst[blockIdx.x * 256 + c] = s;
}

__global__ void ln_k(const float* __restrict__ part, int nch, float invRows,
                     const float* __restrict__ lng, const float* __restrict__ lnb,
                     float* __restrict__ cvec)
{
    __shared__ float red[256];
    int b = blockIdx.x, c = threadIdx.x;
    float um = 0.f;
    for (int i = 0; i < nch; i++) um += part[(b * nch + i) * 256 + c];
    um *= invRows;
    red[c] = um; __syncthreads();
    for (int st = 128; st; st >>= 1) { if (c < st) red[c] += red[c + st]; __syncthreads(); }
    float mean = red[0] * (1.f / 256.f);
    __syncthreads();
    float dv = um - mean;
    red[c] = dv * dv; __syncthreads();
    for (int st = 128; st; st >>= 1) { if (c < st) red[c] += red[c + st]; __syncthreads(); }
    float var = red[0] * (1.f / 256.f);
    cvec[b * 256 + c] = dv * rsqrtf(var + 1e-5f) * lng[c] + lnb[c];
}

__global__ void cpart_k(const float* __restrict__ cvec,
                        const float* __restrict__ Wf, const float* __restrict__ Ww,
                        const float* __restrict__ Wo,
                        const float* __restrict__ bf, const float* __restrict__ bw,
                        const float* __restrict__ bo, float* __restrict__ cp)
{
    int b = blockIdx.x / 3, seg = blockIdx.x % 3;
    int jj = threadIdx.x;
    const float* W  = seg == 0 ? Wf : (seg == 1 ? Ww : Wo);
    const float* bi = seg == 0 ? bf : (seg == 1 ? bw : bo);
    float acc = bi[jj];
    const float* cv = cvec + b * 256;
    for (int cc = 0; cc < 256; cc++) acc = fmaf(cv[cc], W[(256 + cc) * 256 + jj], acc);
    cp[b * 768 + seg * 256 + jj] = acc;
}

// ---------------- scans ------------------------------------------------------
__global__ void scan_aggr_k(const float* __restrict__ G, const float* __restrict__ U,
                            float* __restrict__ chA, float* __restrict__ chB, int backward)
{
    int w = blockIdx.x * 8 + (threadIdx.x >> 5);
    int lane = threadIdx.x & 31;
    int c  = ((w & 7) << 5) + lane;
    int ch = (w >> 3) & 15;
    int b  = w >> 7;
    float s = 0.f, Ap = 1.f;
    int n0 = ch << 8;
#pragma unroll 4
    for (int r = 0; r < 256; r++) {
        int n = backward ? (n0 + 255 - r) : (n0 + r);
        size_t row = (size_t)(b * 4096 + n);
        float d  = fminf(G[row * 768 + c], 80.f);
        float wl = G[row * 768 + 256 + c];
        float uu = U[row * 256 + c];
        float e = __expf(d);
        float inv = __fdividef(1.f, 1.f + e);
        float bb = (e * inv) * sigf(wl) * uu;
        s = fmaf(inv, s, bb);
        Ap *= inv;
    }
    int o = (b * 16 + ch) * 256 + c;
    chA[o] = Ap; chB[o] = s;
}

__global__ void scan_comb_k(const float* __restrict__ chA, const float* __restrict__ chB,
                            float* __restrict__ carry, int backward)
{
    int b = blockIdx.x, c = threadIdx.x;
    float s = 0.f;
    for (int i = 0; i < 16; i++) {
        int ch = backward ? 15 - i : i;
        int o = (b * 16 + ch) * 256 + c;
        carry[o] = s;
        s = fmaf(chA[o], s, chB[o]);
    }
}

__global__ void scan_fin_k(const float* __restrict__ G, const float* __restrict__ U,
                           const float* __restrict__ carry, float* __restrict__ Y, int backward)
{
    int w = blockIdx.x * 8 + (threadIdx.x >> 5);
    int lane = threadIdx.x & 31;
    int c  = ((w & 7) << 5) + lane;
    int ch = (w >> 3) & 15;
    int b  = w >> 7;
    float s = carry[(b * 16 + ch) * 256 + c];
    int n0 = ch << 8;
#pragma unroll 4
    for (int r = 0; r < 256; r++) {
        int n = backward ? (n0 + 255 - r) : (n0 + r);
        size_t row = (size_t)(b * 4096 + n);
        float d  = fminf(G[row * 768 + c], 80.f);
        float wl = G[row * 768 + 256 + c];
        float ol = G[row * 768 + 512 + c];
        float uu = U[row * 256 + c];
        float e = __expf(d);
        float inv = __fdividef(1.f, 1.f + e);
        float bb = (e * inv) * sigf(wl) * uu;
        s = fmaf(inv, s, bb);
        float o = sigf(ol);
        Y[row * 256 + c] = o * s + (1.f - o) * uu;
    }
}

__global__ void scan_global_k(const float* __restrict__ G, const float* __restrict__ U,
                              float* __restrict__ Y)
{
    int b = blockIdx.x, c = threadIdx.x;
    float s = 0.f;
    for (int n = 0; n < 256; n++) {
        size_t row = (size_t)(b * 256 + n);
        float d  = fminf(G[row * 768 + c], 80.f);
        float wl = G[row * 768 + 256 + c];
        float ol = G[row * 768 + 512 + c];
        float uu = U[row * 256 + c];
        float e = __expf(d);
        float inv = __fdividef(1.f, 1.f + e);
        float bb = (e * inv) * sigf(wl) * uu;
        s = fmaf(inv, s, bb);
        float o = sigf(ol);
        Y[row * 256 + c] = o * s + (1.f - o) * uu;
    }
}

// ---------------------------------------------------------------------------
extern "C" void kernel_launch(void* const* d_in, const int* in_sizes, int n_in,
                              void* d_out, int out_size)
{
    const float* x    = (const float*)d_in[0];
    const float* Wt   = (const float*)d_in[1];
    const float* bt   = (const float*)d_in[2];
    const float* posf = (const float*)d_in[3];
    const float* posg = (const float*)d_in[4];
    const float* lng  = (const float*)d_in[5];
    const float* lnb  = (const float*)d_in[6];
    const float* Wf   = (const float*)d_in[7];
    const float* bf   = (const float*)d_in[8];
    const float* Ww   = (const float*)d_in[9];
    const float* bw   = (const float*)d_in[10];
    const float* Wo   = (const float*)d_in[11];
    const float* bo   = (const float*)d_in[12];
    const float* Wr   = (const float*)d_in[13];
    const float* br   = (const float*)d_in[14];
    const float* Wgi  = (const float*)d_in[15];
    const float* bgi  = (const float*)d_in[16];
    const float* dww  = (const float*)d_in[17];
    const float* dwb  = (const float*)d_in[18];
    const float* Wl   = (const float*)d_in[19];
    const float* bl   = (const float*)d_in[20];
    const float* Wlf  = (const float*)d_in[21];
    const float* blf  = (const float*)d_in[22];
    const float* Wout = (const float*)d_in[23];
    const float* bout = (const float*)d_in[24];
    float* out = (float*)d_out;

    float *pu, *pG, *pyf, *pyb, *py, *pyg_up, *pv, *pvmap, *pxseq, *pvmseq,
          *pposf, *pposg, *pxg, *pxgseq, *pug, *pGg, *pyg, *ppum, *ppumg,
          *pcvec, *pcvecg, *pcpart, *pcpartg, *pchA, *pchB, *pcar;
    __nv_bfloat16* pBT;
    cudaGetSymbolAddress((void**)&pu, g_u);
    cudaGetSymbolAddress((void**)&pG, g_G);
    cudaGetSymbolAddress((void**)&pyf, g_yf);
    cudaGetSymbolAddress((void**)&pyb, g_yb);
    cudaGetSymbolAddress((void**)&py, g_y);
    cudaGetSymbolAddress((void**)&pyg_up, g_ygup);
    cudaGetSymbolAddress((void**)&pv, g_v);
    cudaGetSymbolAddress((void**)&pvmap, g_vmap);
    cudaGetSymbolAddress((void**)&pxseq, g_xseq);
    cudaGetSymbolAddress((void**)&pvmseq, g_vmseq);
    cudaGetSymbolAddress((void**)&pposf, g_posf);
    cudaGetSymbolAddress((void**)&pposg, g_posg);
    cudaGetSymbolAddress((void**)&pxg, g_xg);
    cudaGetSymbolAddress((void**)&pxgseq, g_xgseq);
    cudaGetSymbolAddress((void**)&pug, g_ug);
    cudaGetSymbolAddress((void**)&pGg, g_Gg);
    cudaGetSymbolAddress((void**)&pyg, g_yg);
    cudaGetSymbolAddress((void**)&ppum, g_pum);
    cudaGetSymbolAddress((void**)&ppumg, g_pumg);
    cudaGetSymbolAddress((void**)&pcvec, g_cvec);
    cudaGetSymbolAddress((void**)&pcvecg, g_cvecg);
    cudaGetSymbolAddress((void**)&pcpart, g_cpart);
    cudaGetSymbolAddress((void**)&pcpartg, g_cpartg);
    cudaGetSymbolAddress((void**)&pchA, g_chA);
    cudaGetSymbolAddress((void**)&pchB, g_chB);
    cudaGetSymbolAddress((void**)&pcar, g_car);
    cudaGetSymbolAddress((void**)&pBT, g_BT);

    // prep
    wprep_k<<<896, 256>>>(Wt, Wf, Ww, Wo, Wr, Wgi, Wl, Wlf, Wout, pBT);
    pos_up_k<<<4096, 256>>>(posf, pposf);
    pos_down_k<<<256, 256>>>(posg, pposg);
    nchw2seq_k<<<dim3(128, 8, 8), 256>>>(x, pxseq, 4096);
    pool_k<<<2048, 256>>>(x, pxg);
    nchw2seq_k<<<dim3(8, 8, 8), 256>>>(pxg, pxgseq, 256);

    // u = xseq@Wt + bt + posf ; u_g likewise
    tgemm_k<<<dim3(2, 256), 256>>>(pxseq, pxseq, pxseq,
        pBT + BT_T, pBT + BT_T, pBT + BT_T, 256, 256, 0, 4096, 256,
        bt, pposf, pposf, x, pu);
    tgemm_k<<<dim3(2, 16), 256>>>(pxgseq, pxgseq, pxgseq,
        pBT + BT_T, pBT + BT_T, pBT + BT_T, 256, 256, 0, 256, 256,
        bt, pposg, pposg, x, pug);

    // LN context + context part of gates
    colsum_k<<<128, 256>>>(pu, ppum, 256);
    ln_k<<<8, 256>>>(ppum, 16, 1.f / 4096.f, lng, lnb, pcvec);
    cpart_k<<<24, 256>>>(pcvec, Wf, Ww, Wo, bf, bw, bo, pcpart);
    colsum_k<<<8, 256>>>(pug, ppumg, 256);
    ln_k<<<8, 256>>>(ppumg, 1, 1.f / 256.f, lng, lnb, pcvecg);
    cpart_k<<<24, 256>>>(pcvecg, Wf, Ww, Wo, bf, bw, bo, pcpartg);

    // gates G = u@Wtop + cpart (768 output cols, 3 weight segments)
    tgemm_k<<<dim3(6, 256), 256>>>(pu, pu, pu,
        pBT + BT_F, pBT + BT_W2, pBT + BT_O, 256, 256, 1, 4096, 768,
        bf, pcpart, pcpart, x, pG);
    tgemm_k<<<dim3(6, 16), 256>>>(pug, pug, pug,
        pBT + BT_F, pBT + BT_W2, pBT + BT_O, 256, 256, 1, 256, 768,
        bf, pcpartg, pcpartg, x, pGg);

    // scans
    scan_aggr_k<<<128, 256>>>(pG, pu, pchA, pchB, 0);
    scan_comb_k<<<8, 256>>>(pchA, pchB, pcar, 0);
    scan_fin_k<<<128, 256>>>(pG, pu, pcar, pyf, 0);
    scan_aggr_k<<<128, 256>>>(pG, pu, pchA, pchB, 1);
    scan_comb_k<<<8, 256>>>(pchA, pchB, pcar, 1);
    scan_fin_k<<<128, 256>>>(pG, pu, pcar, pyb, 1);
    scan_global_k<<<8, 256>>>(pGg, pug, pyg);

    // rho combine: y = rho*yf + (1-rho)*yb  (K=768, A chunks u,yf,yb)
    tgemm_k<<<dim3(2, 256), 256>>>(pu, pyf, pyb,
        pBT + BT_R, pBT + BT_R, pBT + BT_R, 768, 768, 2, 4096, 256,
        br, pyf, pyb, x, py);

    yg_up_k<<<32768, 256>>>(pyg, pyg_up);

    // lam combine: z = y + lam*ygup (into pyb)
    tgemm_k<<<dim3(2, 256), 256>>>(py, pyg_up, pu,
        pBT + BT_GI, pBT + BT_GI, pBT + BT_GI, 768, 768, 3, 4096, 256,
        bgi, py, pyg_up, x, pyb);

    // local branch
    dwconv_k<<<32768, 256>>>(x, dww, dwb, pvmap);
    nchw2seq_k<<<dim3(128, 8, 8), 256>>>(pvmap, pvmseq, 4096);
    tgemm_k<<<dim3(2, 256), 256>>>(pvmseq, pvmseq, pvmseq,
        pBT + BT_L, pBT + BT_L, pBT + BT_L, 256, 256, 6, 4096, 256,
        bl, py, py, x, pv);

    // eta combine: u_out = eta*v + (1-eta)*z  (into pyf)
    tgemm_k<<<dim3(2, 256), 256>>>(pv, pyb, pyb,
        pBT + BT_LF, pBT + BT_LF, pBT + BT_LF, 512, 512, 4, 4096, 256,
        blf, pv, pyb, x, pyf);

    // out-proj + residual -> NCHW
    tgemm_k<<<dim3(2, 256), 256>>>(pyf, pyf, pyf,
        pBT + BT_OUT, pBT + BT_OUT, pBT + BT_OUT, 256, 256, 5, 4096, 256,
        bout, py, py, x, out);
}